// round 4
// baseline (speedup 1.0000x reference)
#include <cuda_runtime.h>

// ---------------------------------------------------------------------------
// ChordProgressionLoss — single fused kernel.
//   Per row: 12-bit pitch-class bitmask from 4 floats; similarity via
//   popcounts; progression penalty via Jaccard vs 8 constant 3-note templates
//   over a 4-row sliding window (staged in shared memory).
//   Each block handles ITERS*TPB contiguous rows; last-arriving block does the
//   deterministic double-precision final reduction and resets the counter.
// ---------------------------------------------------------------------------

#define TPB   256
#define ITERS 8
#define ROWS_PER_BLOCK (TPB * ITERS)
#define MAX_BLOCKS 4608

__device__ float2       g_partials[MAX_BLOCKS];
__device__ unsigned int g_count = 0;

// MAJOR: (0,4,7) (5,9,0) (7,11,2) (0,4,7)
// MINOR: (0,3,7) (5,8,0) (7,10,2) (0,3,7)
__constant__ unsigned c_major[4] = {0x091u, 0x221u, 0x884u, 0x091u};
__constant__ unsigned c_minor[4] = {0x089u, 0x121u, 0x484u, 0x089u};

__device__ __forceinline__ unsigned pc_bits(const float* __restrict__ base, int row) {
    float4 v = *reinterpret_cast<const float4*>(base + 4 * (size_t)row);
    unsigned b = 0;
    b |= 1u << (((int)v.x) % 12);
    b |= 1u << (((int)v.y) % 12);
    b |= 1u << (((int)v.z) % 12);
    b |= 1u << (((int)v.w) % 12);
    return b;
}

__device__ __forceinline__ float jaccard_d(unsigned b, unsigned tmpl) {
    int inter = __popc(b & tmpl);
    int sp    = __popc(b);
    float uni = (float)(sp + 3 - inter);
    return 1.0f - (float)inter / (uni + 1e-8f);
}

__global__ __launch_bounds__(TPB)
void chord_fused_kernel(const float* __restrict__ pred,
                        const float* __restrict__ targ,
                        float* __restrict__ out,
                        int T, int nBlocks) {
    __shared__ unsigned s_pb[TPB + 3];
    __shared__ float    s_red[2 * (TPB / 32)];
    __shared__ int      s_last;

    const int lane = threadIdx.x & 31;
    const int wid  = threadIdx.x >> 5;
    const int base = blockIdx.x * ROWS_PER_BLOCK;

    float sim_acc = 0.0f;
    float pen_acc = 0.0f;

    #pragma unroll
    for (int it = 0; it < ITERS; ++it) {
        const int t = base + it * TPB + threadIdx.x;
        __syncthreads();  // protect s_pb from previous iteration's readers

        unsigned pb = 0;
        if (t < T) {
            pb = pc_bits(pred, t);
            s_pb[threadIdx.x] = pb;
            if (threadIdx.x < 3) {
                int t2 = t + TPB;
                s_pb[TPB + threadIdx.x] = (t2 < T) ? pc_bits(pred, t2) : 0u;
            }
        }
        __syncthreads();

        if (t < T) {
            // ---- similarity ----
            unsigned tb = pc_bits(targ, t);
            const float eps = 1e-6f;
            float sp = (float)__popc(pb);
            float st = (float)__popc(tb);
            float in = (float)__popc(pb & tb);
            float num = in + eps * (sp + st) + 12.0f * eps * eps;
            float s   = num / ((sp + 12.0f * eps) * (st + 12.0f * eps));
            sim_acc += fminf(fmaxf(s, 0.0f), 1.0f);

            // ---- progression penalty (window at t) ----
            if (t < T - 3) {
                float maj = 0.0f, mino = 0.0f;
                #pragma unroll
                for (int j = 0; j < 4; j++) {
                    unsigned bj = s_pb[threadIdx.x + j];
                    maj  += jaccard_d(bj, c_major[j]);
                    mino += jaccard_d(bj, c_minor[j]);
                }
                pen_acc += fminf(maj * 0.25f, mino * 0.25f);
            }
        }
    }

    // ---- block reduction of (sim_acc, pen_acc) ----
    #pragma unroll
    for (int off = 16; off > 0; off >>= 1) {
        sim_acc += __shfl_down_sync(0xFFFFFFFFu, sim_acc, off);
        pen_acc += __shfl_down_sync(0xFFFFFFFFu, pen_acc, off);
    }
    if (lane == 0) {
        s_red[wid]             = sim_acc;
        s_red[TPB / 32 + wid]  = pen_acc;
    }
    __syncthreads();
    if (wid == 0) {
        float vs = (lane < TPB / 32) ? s_red[lane]            : 0.0f;
        float vp = (lane < TPB / 32) ? s_red[TPB / 32 + lane] : 0.0f;
        #pragma unroll
        for (int off = 4; off > 0; off >>= 1) {
            vs += __shfl_down_sync(0xFFFFFFFFu, vs, off);
            vp += __shfl_down_sync(0xFFFFFFFFu, vp, off);
        }
        if (lane == 0) {
            g_partials[blockIdx.x] = make_float2(vs, vp);
            __threadfence();
            unsigned done = atomicAdd(&g_count, 1u);
            s_last = (done == (unsigned)(nBlocks - 1)) ? 1 : 0;
        }
    }
    __syncthreads();

    // ---- last-arriving block: deterministic final reduction ----
    if (s_last) {
        double s = 0.0, p = 0.0;
        for (int i = threadIdx.x; i < nBlocks; i += TPB) {
            float2 v = g_partials[i];
            s += (double)v.x;
            p += (double)v.y;
        }
        #pragma unroll
        for (int off = 16; off > 0; off >>= 1) {
            s += __shfl_down_sync(0xFFFFFFFFu, s, off);
            p += __shfl_down_sync(0xFFFFFFFFu, p, off);
        }
        __shared__ double d_s[TPB / 32], d_p[TPB / 32];
        if (lane == 0) { d_s[wid] = s; d_p[wid] = p; }
        __syncthreads();
        if (wid == 0) {
            s = (lane < TPB / 32) ? d_s[lane] : 0.0;
            p = (lane < TPB / 32) ? d_p[lane] : 0.0;
            #pragma unroll
            for (int off = 4; off > 0; off >>= 1) {
                s += __shfl_down_sync(0xFFFFFFFFu, s, off);
                p += __shfl_down_sync(0xFFFFFFFFu, p, off);
            }
            if (lane == 0) {
                double sim_loss = 1.0 - s / (double)T;
                double prog     = p / (double)(T - 3);
                out[0] = (float)(sim_loss + 0.5 * prog);
                g_count = 0;  // reset for next graph replay
            }
        }
    }
}

extern "C" void kernel_launch(void* const* d_in, const int* in_sizes, int n_in,
                              void* d_out, int out_size) {
    const float* pred = (const float*)d_in[0];
    const float* targ = (const float*)d_in[1];
    int T = in_sizes[0] / 4;

    int nBlocks = (T + ROWS_PER_BLOCK - 1) / ROWS_PER_BLOCK;
    chord_fused_kernel<<<nBlocks, TPB>>>(pred, targ, (float*)d_out, T, nBlocks);
}